// round 7
// baseline (speedup 1.0000x reference)
#include <cuda_runtime.h>
#include <cuda_fp16.h>
#include <cstdint>

// ---------------- problem constants ----------------
constexpr int Dd   = 768;
constexpr int RS   = 256 * 768;            // row stride in floats (B*D)
constexpr int TEXT_ELEMS   = 77 * 256 * 768;
constexpr int VISION_ELEMS = 576 * 256 * 768;

// ---------------- smem layout (32-bit word offsets), per-CTA (M-half) ----------------
constexpr int S_STR = 580;                 // S row stride (fp32)
constexpr int STG   = 39 * S_STR + 12;     // 22632 words (16B aligned)
// phase-1 half2 tiles (1 word = 1 half2), k-pair stride 12 (8 pairs + pad 4)
constexpr int P1_TH = STG;                 // 48 x 12
constexpr int P1_TL = P1_TH + 48 * 12;
constexpr int P1_VH = P1_TL + 48 * 12;     // 192 x 12
constexpr int P1_VL = P1_VH + 192 * 12;
constexpr int P1_END = P1_VL + 192 * 12;   // STG + 5760 = 28392
// phase-2 half2 V tiles: [d=128][pair stride 20]
constexpr int P2_VH = STG;                 // 128 x 20
constexpr int P2_VL = P2_VH + 128 * 20;
constexpr int P2_END = P2_VL + 128 * 20;   // STG + 5120
constexpr int SMEM_WORDS = (P1_END > P2_END ? P1_END : P2_END);  // 28392
constexpr int SMEM_BYTES = SMEM_WORDS * 4; // 113568 B -> 2 CTAs/SM

__device__ __forceinline__ float ex2f(float x) {
    float y; asm("ex2.approx.f32 %0, %1;" : "=f"(y) : "f"(x)); return y;
}

// split a float2 into hi (fp16x2) and lo (fp16x2 of residual), packed as u32
__device__ __forceinline__ void split2(float2 x, uint32_t& h, uint32_t& l) {
    __half hx = __float2half_rn(x.x), hy = __float2half_rn(x.y);
    __half lx = __float2half_rn(x.x - __half2float(hx));
    __half ly = __float2half_rn(x.y - __half2float(hy));
    h = (uint32_t)__half_as_ushort(hx) | ((uint32_t)__half_as_ushort(hy) << 16);
    l = (uint32_t)__half_as_ushort(lx) | ((uint32_t)__half_as_ushort(ly) << 16);
}

// fp16 m16n8k16, fp32 accumulate
__device__ __forceinline__ void mma16(float* c,
                                      uint32_t a0, uint32_t a1, uint32_t a2, uint32_t a3,
                                      uint32_t b0, uint32_t b1) {
    asm volatile(
        "mma.sync.aligned.m16n8k16.row.col.f32.f16.f16.f32 "
        "{%0,%1,%2,%3}, {%4,%5,%6,%7}, {%8,%9}, {%0,%1,%2,%3};\n"
        : "+f"(c[0]), "+f"(c[1]), "+f"(c[2]), "+f"(c[3])
        : "r"(a0), "r"(a1), "r"(a2), "r"(a3), "r"(b0), "r"(b1));
}

extern __shared__ float sm[];

__global__ __launch_bounds__(256, 2)
void ShallowDecoder_kernel(const float* __restrict__ text,
                           const float* __restrict__ vision,
                           float* __restrict__ out) {
    const int b    = blockIdx.x >> 1;
    const int half = blockIdx.x & 1;
    const int mbase = half * 39;
    const int Mreal = half ? 38 : 39;

    const float* tb = text + (size_t)b * Dd + (size_t)mbase * RS;
    const float* vb = vision + (size_t)b * Dd;
    float* ob = out + (size_t)b * Dd + (size_t)mbase * RS;

    uint32_t* smu = (uint32_t*)sm;

    const int tid  = threadIdx.x;
    const int w    = tid >> 5;    // 0..7
    const int lane = tid & 31;
    const int g    = lane >> 2;   // groupID
    const int c    = lane & 3;    // threadID_in_group

    // ================= Phase 1: S = T V^T (3xFP16, m16n8k16), N-tile 192 =================
    const int TLIM = Mreal * 8;   // float2 count for T chunk
    for (int nt = 0; nt < 3; ++nt) {
        const int nb = nt * 192;

        float acc[3][3][4];
        #pragma unroll
        for (int mt = 0; mt < 3; ++mt)
            #pragma unroll
            for (int nc = 0; nc < 3; ++nc)
                #pragma unroll
                for (int q = 0; q < 4; ++q) acc[mt][nc][q] = 0.f;

        float2 pT[2], pV[6];
        // prefetch chunk 0 (chunk = 16 floats = 8 k-pairs)
        #pragma unroll
        for (int q = 0; q < 2; ++q) {
            int i = tid + 256 * q;
            if (i < TLIM) {
                int m = i >> 3, j = i & 7;
                pT[q] = *(const float2*)(tb + (size_t)m * RS + 2 * j);
            }
        }
        #pragma unroll
        for (int q = 0; q < 6; ++q) {
            int i = tid + 256 * q;        // 0..1535
            int m = i >> 3, j = i & 7;    // m 0..191
            pV[q] = *(const float2*)(vb + (size_t)(nb + m) * RS + 2 * j);
        }

        for (int dc = 0; dc < 48; ++dc) {
            // stage prefetched regs -> smem hi/lo half2 tiles
            #pragma unroll
            for (int q = 0; q < 2; ++q) {
                int i = tid + 256 * q;
                if (i < TLIM) {
                    int m = i >> 3, j = i & 7;
                    uint32_t h, l;
                    split2(pT[q], h, l);
                    smu[P1_TH + m * 12 + j] = h;
                    smu[P1_TL + m * 12 + j] = l;
                }
            }
            #pragma unroll
            for (int q = 0; q < 6; ++q) {
                int i = tid + 256 * q;
                int m = i >> 3, j = i & 7;
                uint32_t h, l;
                split2(pV[q], h, l);
                smu[P1_VH + m * 12 + j] = h;
                smu[P1_VL + m * 12 + j] = l;
            }
            __syncthreads();

            // prefetch next chunk while mma runs
            if (dc < 47) {
                const int d0 = (dc + 1) * 16;
                #pragma unroll
                for (int q = 0; q < 2; ++q) {
                    int i = tid + 256 * q;
                    if (i < TLIM) {
                        int m = i >> 3, j = i & 7;
                        pT[q] = *(const float2*)(tb + (size_t)m * RS + d0 + 2 * j);
                    }
                }
                #pragma unroll
                for (int q = 0; q < 6; ++q) {
                    int i = tid + 256 * q;
                    int m = i >> 3, j = i & 7;
                    pV[q] = *(const float2*)(vb + (size_t)(nb + m) * RS + d0 + 2 * j);
                }
            }

            // one k16 step per chunk
            uint32_t bh0[3], bh1[3], bl0[3], bl1[3];
            #pragma unroll
            for (int nc = 0; nc < 3; ++nc) {
                int row = w * 24 + nc * 8 + g;
                int ba  = row * 12 + c;
                bh0[nc] = smu[P1_VH + ba];     bh1[nc] = smu[P1_VH + ba + 4];
                bl0[nc] = smu[P1_VL + ba];     bl1[nc] = smu[P1_VL + ba + 4];
            }
            #pragma unroll
            for (int mt = 0; mt < 3; ++mt) {
                int r  = mt * 16 + g;
                int aa = r * 12 + c;
                uint32_t ah0 = smu[P1_TH + aa];
                uint32_t ah1 = smu[P1_TH + aa + 8 * 12];
                uint32_t ah2 = smu[P1_TH + aa + 4];
                uint32_t ah3 = smu[P1_TH + aa + 8 * 12 + 4];
                uint32_t al0 = smu[P1_TL + aa];
                uint32_t al1 = smu[P1_TL + aa + 8 * 12];
                uint32_t al2 = smu[P1_TL + aa + 4];
                uint32_t al3 = smu[P1_TL + aa + 8 * 12 + 4];
                #pragma unroll
                for (int nc = 0; nc < 3; ++nc) {
                    mma16(acc[mt][nc], ah0, ah1, ah2, ah3, bh0[nc], bh1[nc]);
                    mma16(acc[mt][nc], ah0, ah1, ah2, ah3, bl0[nc], bl1[nc]);
                    mma16(acc[mt][nc], al0, al1, al2, al3, bh0[nc], bh1[nc]);
                }
            }
            __syncthreads();
        }

        // store S tile (guard rows < Mreal)
        #pragma unroll
        for (int mt = 0; mt < 3; ++mt) {
            int r0 = mt * 16 + g, r1 = r0 + 8;
            #pragma unroll
            for (int nc = 0; nc < 3; ++nc) {
                int col = nb + w * 24 + nc * 8 + 2 * c;
                if (r0 < Mreal)
                    *(float2*)&sm[r0 * S_STR + col] =
                        make_float2(acc[mt][nc][0], acc[mt][nc][1]);
                if (r1 < Mreal)
                    *(float2*)&sm[r1 * S_STR + col] =
                        make_float2(acc[mt][nc][2], acc[mt][nc][3]);
            }
        }
    }
    __syncthreads();

    // ================= Softmax over n (576), temp 0.07 =================
    {
        const float SCL = 20.60992915555662f; // log2(e)/0.07
        for (int r = w; r < Mreal; r += 8) {
            float v[18];
            float mx = -1e30f;
            #pragma unroll
            for (int j = 0; j < 18; ++j) {
                v[j] = sm[r * S_STR + lane + 32 * j];
                mx = fmaxf(mx, v[j]);
            }
            #pragma unroll
            for (int o = 16; o > 0; o >>= 1)
                mx = fmaxf(mx, __shfl_xor_sync(0xffffffffu, mx, o));
            float sum = 0.f;
            #pragma unroll
            for (int j = 0; j < 18; ++j) {
                v[j] = ex2f((v[j] - mx) * SCL);
                sum += v[j];
            }
            #pragma unroll
            for (int o = 16; o > 0; o >>= 1)
                sum += __shfl_xor_sync(0xffffffffu, sum, o);
            float rinv = 1.0f / sum;
            #pragma unroll
            for (int j = 0; j < 18; ++j)
                sm[r * S_STR + lane + 32 * j] = v[j] * rinv;
        }
    }
    __syncthreads();

    // ================= Phase 2: O = A V (3xFP16, m16n8k16), d-tile 128 =================
    int arow[3][2];
    #pragma unroll
    for (int mt = 0; mt < 3; ++mt) {
        int r0 = mt * 16 + g;
        int r1 = r0 + 8;
        arow[mt][0] = (r0 >= Mreal ? Mreal - 1 : r0) * S_STR;
        arow[mt][1] = (r1 >= Mreal ? Mreal - 1 : r1) * S_STR;
    }

    for (int dt = 0; dt < 6; ++dt) {
        const int db = dt * 128;

        float acc[3][2][4];
        #pragma unroll
        for (int mt = 0; mt < 3; ++mt)
            #pragma unroll
            for (int d8 = 0; d8 < 2; ++d8)
                #pragma unroll
                for (int q = 0; q < 4; ++q) acc[mt][d8][q] = 0.f;

        // V staging: warp w handles n-pairs {w, w+8}; lanes sweep d (4 x 32)
        float px[2][4], py[2][4];
        #pragma unroll
        for (int s = 0; s < 2; ++s) {
            int n0 = 2 * (w + 8 * s);
            #pragma unroll
            for (int it = 0; it < 4; ++it) {
                int d = lane + 32 * it;
                px[s][it] = vb[(size_t)n0 * RS + db + d];
                py[s][it] = vb[(size_t)(n0 + 1) * RS + db + d];
            }
        }

        for (int ch = 0; ch < 18; ++ch) {
            #pragma unroll
            for (int s = 0; s < 2; ++s) {
                int pp = w + 8 * s;
                #pragma unroll
                for (int it = 0; it < 4; ++it) {
                    int d = lane + 32 * it;
                    uint32_t h, l;
                    split2(make_float2(px[s][it], py[s][it]), h, l);
                    smu[P2_VH + d * 20 + pp] = h;
                    smu[P2_VL + d * 20 + pp] = l;
                }
            }
            __syncthreads();

            if (ch < 17) {
                #pragma unroll
                for (int s = 0; s < 2; ++s) {
                    int n0 = (ch + 1) * 32 + 2 * (w + 8 * s);
                    #pragma unroll
                    for (int it = 0; it < 4; ++it) {
                        int d = lane + 32 * it;
                        px[s][it] = vb[(size_t)n0 * RS + db + d];
                        py[s][it] = vb[(size_t)(n0 + 1) * RS + db + d];
                    }
                }
            }

            const int nbase = ch * 32;
            #pragma unroll
            for (int kk = 0; kk < 2; ++kk) {
                uint32_t bh0[2], bh1[2], bl0[2], bl1[2];
                #pragma unroll
                for (int d8 = 0; d8 < 2; ++d8) {
                    int col = w * 16 + d8 * 8 + g;
                    int bp  = kk * 8 + c;
                    bh0[d8] = smu[P2_VH + col * 20 + bp];
                    bh1[d8] = smu[P2_VH + col * 20 + bp + 4];
                    bl0[d8] = smu[P2_VL + col * 20 + bp];
                    bl1[d8] = smu[P2_VL + col * 20 + bp + 4];
                }
                #pragma unroll
                for (int mt = 0; mt < 3; ++mt) {
                    int ca = nbase + kk * 16 + 2 * c;
                    float2 f0 = *(float2*)&sm[arow[mt][0] + ca];
                    float2 f1 = *(float2*)&sm[arow[mt][1] + ca];
                    float2 f2 = *(float2*)&sm[arow[mt][0] + ca + 8];
                    float2 f3 = *(float2*)&sm[arow[mt][1] + ca + 8];
                    uint32_t ah0, al0, ah1, al1, ah2, al2, ah3, al3;
                    split2(f0, ah0, al0);
                    split2(f1, ah1, al1);
                    split2(f2, ah2, al2);
                    split2(f3, ah3, al3);
                    #pragma unroll
                    for (int d8 = 0; d8 < 2; ++d8) {
                        mma16(acc[mt][d8], ah0, ah1, ah2, ah3, bh0[d8], bh1[d8]);
                        mma16(acc[mt][d8], ah0, ah1, ah2, ah3, bl0[d8], bl1[d8]);
                        mma16(acc[mt][d8], al0, al1, al2, al3, bh0[d8], bh1[d8]);
                    }
                }
            }
            __syncthreads();
        }

        // store output tile (fp32, guard rows < Mreal)
        #pragma unroll
        for (int mt = 0; mt < 3; ++mt) {
            int r0 = mt * 16 + g, r1 = r0 + 8;
            #pragma unroll
            for (int d8 = 0; d8 < 2; ++d8) {
                int col = db + w * 16 + d8 * 8 + 2 * c;
                if (r0 < Mreal)
                    *(float2*)(ob + (size_t)r0 * RS + col) =
                        make_float2(acc[mt][d8][0], acc[mt][d8][1]);
                if (r1 < Mreal)
                    *(float2*)(ob + (size_t)r1 * RS + col) =
                        make_float2(acc[mt][d8][2], acc[mt][d8][3]);
            }
        }
    }
}

extern "C" void kernel_launch(void* const* d_in, const int* in_sizes, int n_in,
                              void* d_out, int out_size) {
    const float* text   = (const float*)d_in[0];
    const float* vision = (const float*)d_in[1];
    if (n_in >= 2 && in_sizes[0] == VISION_ELEMS && in_sizes[1] == TEXT_ELEMS) {
        const float* t = text; text = vision; vision = t;
    }
    cudaFuncSetAttribute(ShallowDecoder_kernel,
                         cudaFuncAttributeMaxDynamicSharedMemorySize, SMEM_BYTES);
    ShallowDecoder_kernel<<<512, 256, SMEM_BYTES>>>(text, vision, (float*)d_out);
}

// round 8
// speedup vs baseline: 1.5626x; 1.5626x over previous
#include <cuda_runtime.h>
#include <cuda_fp16.h>
#include <cstdint>

// ---------------- problem constants ----------------
constexpr int Dd   = 768;
constexpr int RS   = 256 * 768;            // row stride in floats (B*D)
constexpr int TEXT_ELEMS   = 77 * 256 * 768;
constexpr int VISION_ELEMS = 576 * 256 * 768;

// ---------------- smem layout (32-bit word offsets) ----------------
constexpr int S_STR = 580;                 // S row stride (fp32) / A hi+lo row container
constexpr int STG   = 77 * S_STR + 12;     // 44672, 16B aligned
// phase-1 half2 stage tiles, chunk = 32 floats = 16 pairs, stride 20 (16 + pad 4)
constexpr int P1_TH = STG;                 // 96 x 20
constexpr int P1_TL = P1_TH + 96 * 20;
constexpr int P1_VH = P1_TL + 96 * 20;     // 192 x 20
constexpr int P1_VL = P1_VH + 192 * 20;
constexpr int P1_END = P1_VL + 192 * 20;   // 44672 + 11520 = 56192
// phase-2 half2 V tiles: [d=192][pair stride 20]
constexpr int P2_VH = STG;                 // 192 x 20
constexpr int P2_VL = P2_VH + 192 * 20;
constexpr int P2_END = P2_VL + 192 * 20;   // 44672 + 7680
constexpr int SMEM_WORDS = (P1_END > P2_END ? P1_END : P2_END);  // 56192
constexpr int SMEM_BYTES = SMEM_WORDS * 4; // 224768 B (< 227 KB cap)

__device__ __forceinline__ float ex2f(float x) {
    float y; asm("ex2.approx.f32 %0, %1;" : "=f"(y) : "f"(x)); return y;
}

// split a float2 into hi (fp16x2) and lo (fp16x2 of residual), packed as u32
__device__ __forceinline__ void split2(float2 x, uint32_t& h, uint32_t& l) {
    __half hx = __float2half_rn(x.x), hy = __float2half_rn(x.y);
    __half lx = __float2half_rn(x.x - __half2float(hx));
    __half ly = __float2half_rn(x.y - __half2float(hy));
    h = (uint32_t)__half_as_ushort(hx) | ((uint32_t)__half_as_ushort(hy) << 16);
    l = (uint32_t)__half_as_ushort(lx) | ((uint32_t)__half_as_ushort(ly) << 16);
}

// fp16 m16n8k16, fp32 accumulate
__device__ __forceinline__ void mma16(float* c,
                                      uint32_t a0, uint32_t a1, uint32_t a2, uint32_t a3,
                                      uint32_t b0, uint32_t b1) {
    asm volatile(
        "mma.sync.aligned.m16n8k16.row.col.f32.f16.f16.f32 "
        "{%0,%1,%2,%3}, {%4,%5,%6,%7}, {%8,%9}, {%0,%1,%2,%3};\n"
        : "+f"(c[0]), "+f"(c[1]), "+f"(c[2]), "+f"(c[3])
        : "r"(a0), "r"(a1), "r"(a2), "r"(a3), "r"(b0), "r"(b1));
}

extern __shared__ float sm[];

__global__ __launch_bounds__(512, 1)
void ShallowDecoder_kernel(const float* __restrict__ text,
                           const float* __restrict__ vision,
                           float* __restrict__ out) {
    const int b = blockIdx.x;
    const float* tb = text + (size_t)b * Dd;
    const float* vb = vision + (size_t)b * Dd;
    float* ob = out + (size_t)b * Dd;

    uint32_t* smu = (uint32_t*)sm;

    const int tid  = threadIdx.x;
    const int w    = tid >> 5;    // 0..15
    const int lane = tid & 31;
    const int wm   = w >> 3;      // 0..1 : 48 M-rows each
    const int wn   = w & 7;       // 0..7
    const int g    = lane >> 2;   // groupID
    const int c    = lane & 3;    // threadID_in_group

    // ======= Phase 1: S = T V^T (3xFP16, m16n8k16), N-tile 192, k-chunk 32 =======
    for (int nt = 0; nt < 3; ++nt) {
        const int nb = nt * 192;

        float acc[3][3][4];
        #pragma unroll
        for (int mt = 0; mt < 3; ++mt)
            #pragma unroll
            for (int nc = 0; nc < 3; ++nc)
                #pragma unroll
                for (int q = 0; q < 4; ++q) acc[mt][nc][q] = 0.f;

        float2 pT[3], pV[6];
        // prefetch chunk 0 (chunk = 32 floats = 16 pairs; 1 float2 = 1 pair)
        #pragma unroll
        for (int q = 0; q < 3; ++q) {
            int i = tid + 512 * q;            // T: 77 rows x 16 pairs = 1232
            if (i < 1232) {
                int m = i >> 4, j = i & 15;
                pT[q] = *(const float2*)(tb + (size_t)m * RS + 2 * j);
            }
        }
        #pragma unroll
        for (int q = 0; q < 6; ++q) {
            int i = tid + 512 * q;            // V: 192 x 16 = 3072
            int m = i >> 4, j = i & 15;
            pV[q] = *(const float2*)(vb + (size_t)(nb + m) * RS + 2 * j);
        }

        for (int dc = 0; dc < 24; ++dc) {
            // stage prefetched regs -> smem hi/lo half2 tiles
            #pragma unroll
            for (int q = 0; q < 3; ++q) {
                int i = tid + 512 * q;
                if (i < 1232) {
                    int m = i >> 4, j = i & 15;
                    uint32_t h, l;
                    split2(pT[q], h, l);
                    smu[P1_TH + m * 20 + j] = h;
                    smu[P1_TL + m * 20 + j] = l;
                }
            }
            #pragma unroll
            for (int q = 0; q < 6; ++q) {
                int i = tid + 512 * q;
                int m = i >> 4, j = i & 15;
                uint32_t h, l;
                split2(pV[q], h, l);
                smu[P1_VH + m * 20 + j] = h;
                smu[P1_VL + m * 20 + j] = l;
            }
            __syncthreads();

            // prefetch next chunk while mma runs
            if (dc < 23) {
                const int d0 = (dc + 1) * 32;
                #pragma unroll
                for (int q = 0; q < 3; ++q) {
                    int i = tid + 512 * q;
                    if (i < 1232) {
                        int m = i >> 4, j = i & 15;
                        pT[q] = *(const float2*)(tb + (size_t)m * RS + d0 + 2 * j);
                    }
                }
                #pragma unroll
                for (int q = 0; q < 6; ++q) {
                    int i = tid + 512 * q;
                    int m = i >> 4, j = i & 15;
                    pV[q] = *(const float2*)(vb + (size_t)(nb + m) * RS + d0 + 2 * j);
                }
            }

            // two k16 steps per chunk
            #pragma unroll
            for (int kk = 0; kk < 2; ++kk) {
                uint32_t bh0[3], bh1[3], bl0[3], bl1[3];
                #pragma unroll
                for (int nc = 0; nc < 3; ++nc) {
                    int row = wn * 24 + nc * 8 + g;
                    int ba  = row * 20 + kk * 8 + c;
                    bh0[nc] = smu[P1_VH + ba];     bh1[nc] = smu[P1_VH + ba + 4];
                    bl0[nc] = smu[P1_VL + ba];     bl1[nc] = smu[P1_VL + ba + 4];
                }
                #pragma unroll
                for (int mt = 0; mt < 3; ++mt) {
                    int r  = wm * 48 + mt * 16 + g;
                    int aa = r * 20 + kk * 8 + c;
                    uint32_t ah0 = smu[P1_TH + aa];
                    uint32_t ah1 = smu[P1_TH + aa + 8 * 20];
                    uint32_t ah2 = smu[P1_TH + aa + 4];
                    uint32_t ah3 = smu[P1_TH + aa + 8 * 20 + 4];
                    uint32_t al0 = smu[P1_TL + aa];
                    uint32_t al1 = smu[P1_TL + aa + 8 * 20];
                    uint32_t al2 = smu[P1_TL + aa + 4];
                    uint32_t al3 = smu[P1_TL + aa + 8 * 20 + 4];
                    #pragma unroll
                    for (int nc = 0; nc < 3; ++nc) {
                        mma16(acc[mt][nc], ah0, ah1, ah2, ah3, bh0[nc], bh1[nc]);
                        mma16(acc[mt][nc], ah0, ah1, ah2, ah3, bl0[nc], bl1[nc]);
                        mma16(acc[mt][nc], al0, al1, al2, al3, bh0[nc], bh1[nc]);
                    }
                }
            }
            __syncthreads();
        }

        // store S tile (fp32, guard rows < 77)
        #pragma unroll
        for (int mt = 0; mt < 3; ++mt) {
            int r0 = wm * 48 + mt * 16 + g, r1 = r0 + 8;
            #pragma unroll
            for (int nc = 0; nc < 3; ++nc) {
                int col = nb + wn * 24 + nc * 8 + 2 * c;
                if (r0 < 77)
                    *(float2*)&sm[r0 * S_STR + col] =
                        make_float2(acc[mt][nc][0], acc[mt][nc][1]);
                if (r1 < 77)
                    *(float2*)&sm[r1 * S_STR + col] =
                        make_float2(acc[mt][nc][2], acc[mt][nc][3]);
            }
        }
    }
    __syncthreads();

    // ===== Softmax over n (576), temp 0.07; writes A pre-split hi/lo in place =====
    // After this block, row r holds: hi half2 pairs at [580r + 0, 288),
    //                                lo half2 pairs at [580r + 288, 576).
    {
        const float SCL = 20.60992915555662f; // log2(e)/0.07
        for (int r = w; r < 77; r += 16) {
            float v[18];
            float mx = -1e30f;
            #pragma unroll
            for (int j = 0; j < 18; ++j) {
                v[j] = sm[r * S_STR + lane + 32 * j];
                mx = fmaxf(mx, v[j]);
            }
            #pragma unroll
            for (int o = 16; o > 0; o >>= 1)
                mx = fmaxf(mx, __shfl_xor_sync(0xffffffffu, mx, o));
            float sum = 0.f;
            #pragma unroll
            for (int j = 0; j < 18; ++j) {
                v[j] = ex2f((v[j] - mx) * SCL);
                sum += v[j];
            }
            #pragma unroll
            for (int o = 16; o > 0; o >>= 1)
                sum += __shfl_xor_sync(0xffffffffu, sum, o);
            float rinv = 1.0f / sum;
            // write probabilities fp32 (smem as lane->pair transpose medium)
            #pragma unroll
            for (int j = 0; j < 18; ++j)
                sm[r * S_STR + lane + 32 * j] = v[j] * rinv;
            __syncwarp();
            // gather pairs (lane owns pairs lane + 32q), then overwrite row with hi/lo
            float2 f[9];
            #pragma unroll
            for (int q = 0; q < 9; ++q)
                f[q] = *(float2*)&sm[r * S_STR + 2 * (lane + 32 * q)];
            __syncwarp();
            #pragma unroll
            for (int q = 0; q < 9; ++q) {
                uint32_t h, l;
                split2(f[q], h, l);
                smu[r * S_STR + lane + 32 * q] = h;
                smu[r * S_STR + 288 + lane + 32 * q] = l;
            }
        }
    }
    __syncthreads();

    // ======= Phase 2: O = A V (3xFP16, m16n8k16), d-tile 192; A pre-split =======
    int arow[3][2];
    #pragma unroll
    for (int mt = 0; mt < 3; ++mt) {
        int r0 = wm * 48 + mt * 16 + g;
        int r1 = r0 + 8;
        arow[mt][0] = (r0 > 76 ? 76 : r0) * S_STR;
        arow[mt][1] = (r1 > 76 ? 76 : r1) * S_STR;
    }

    for (int dt = 0; dt < 4; ++dt) {
        const int db = dt * 192;

        float acc[3][3][4];
        #pragma unroll
        for (int mt = 0; mt < 3; ++mt)
            #pragma unroll
            for (int d8 = 0; d8 < 3; ++d8)
                #pragma unroll
                for (int q = 0; q < 4; ++q) acc[mt][d8][q] = 0.f;

        // V staging: warp w <-> n-pair w (16 pairs per 32-n chunk); lanes sweep d
        float pv0[6], pv1[6];
        #pragma unroll
        for (int it = 0; it < 6; ++it) {
            int d = lane + 32 * it;
            pv0[it] = vb[(size_t)(2 * w) * RS + db + d];
            pv1[it] = vb[(size_t)(2 * w + 1) * RS + db + d];
        }

        for (int ch = 0; ch < 18; ++ch) {
            #pragma unroll
            for (int it = 0; it < 6; ++it) {
                int d = lane + 32 * it;
                uint32_t h, l;
                split2(make_float2(pv0[it], pv1[it]), h, l);
                smu[P2_VH + d * 20 + w] = h;
                smu[P2_VL + d * 20 + w] = l;
            }
            __syncthreads();

            if (ch < 17) {
                const int n0 = (ch + 1) * 32 + 2 * w;
                #pragma unroll
                for (int it = 0; it < 6; ++it) {
                    int d = lane + 32 * it;
                    pv0[it] = vb[(size_t)n0 * RS + db + d];
                    pv1[it] = vb[(size_t)(n0 + 1) * RS + db + d];
                }
            }

            #pragma unroll
            for (int kk = 0; kk < 2; ++kk) {
                uint32_t bh0[3], bh1[3], bl0[3], bl1[3];
                #pragma unroll
                for (int d8 = 0; d8 < 3; ++d8) {
                    int col = wn * 24 + d8 * 8 + g;
                    int bp  = kk * 8 + c;
                    bh0[d8] = smu[P2_VH + col * 20 + bp];
                    bh1[d8] = smu[P2_VH + col * 20 + bp + 4];
                    bl0[d8] = smu[P2_VL + col * 20 + bp];
                    bl1[d8] = smu[P2_VL + col * 20 + bp + 4];
                }
                const int pb = ch * 16 + kk * 8 + c;   // pair index within row
                #pragma unroll
                for (int mt = 0; mt < 3; ++mt) {
                    uint32_t ah0 = smu[arow[mt][0] + pb];
                    uint32_t ah1 = smu[arow[mt][1] + pb];
                    uint32_t ah2 = smu[arow[mt][0] + pb + 4];
                    uint32_t ah3 = smu[arow[mt][1] + pb + 4];
                    uint32_t al0 = smu[arow[mt][0] + 288 + pb];
                    uint32_t al1 = smu[arow[mt][1] + 288 + pb];
                    uint32_t al2 = smu[arow[mt][0] + 288 + pb + 4];
                    uint32_t al3 = smu[arow[mt][1] + 288 + pb + 4];
                    #pragma unroll
                    for (int d8 = 0; d8 < 3; ++d8) {
                        mma16(acc[mt][d8], ah0, ah1, ah2, ah3, bh0[d8], bh1[d8]);
                        mma16(acc[mt][d8], ah0, ah1, ah2, ah3, bl0[d8], bl1[d8]);
                        mma16(acc[mt][d8], al0, al1, al2, al3, bh0[d8], bh1[d8]);
                    }
                }
            }
            __syncthreads();
        }

        // store output tile (fp32, guard rows < 77)
        #pragma unroll
        for (int mt = 0; mt < 3; ++mt) {
            int r0 = wm * 48 + mt * 16 + g, r1 = r0 + 8;
            #pragma unroll
            for (int d8 = 0; d8 < 3; ++d8) {
                int col = db + wn * 24 + d8 * 8 + 2 * c;
                if (r0 < 77)
                    *(float2*)(ob + (size_t)r0 * RS + col) =
                        make_float2(acc[mt][d8][0], acc[mt][d8][1]);
                if (r1 < 77)
                    *(float2*)(ob + (size_t)r1 * RS + col) =
                        make_float2(acc[mt][d8][2], acc[mt][d8][3]);
            }
        }
    }
}

extern "C" void kernel_launch(void* const* d_in, const int* in_sizes, int n_in,
                              void* d_out, int out_size) {
    const float* text   = (const float*)d_in[0];
    const float* vision = (const float*)d_in[1];
    if (n_in >= 2 && in_sizes[0] == VISION_ELEMS && in_sizes[1] == TEXT_ELEMS) {
        const float* t = text; text = vision; vision = t;
    }
    cudaFuncSetAttribute(ShallowDecoder_kernel,
                         cudaFuncAttributeMaxDynamicSharedMemorySize, SMEM_BYTES);
    ShallowDecoder_kernel<<<256, 512, SMEM_BYTES>>>(text, vision, (float*)d_out);
}

// round 10
// speedup vs baseline: 1.9744x; 1.2635x over previous
#include <cuda_runtime.h>
#include <cuda_fp16.h>
#include <cstdint>

// ---------------- problem constants ----------------
constexpr int Dd   = 768;
constexpr int RS   = 256 * 768;            // row stride in floats (B*D)
constexpr int TEXT_ELEMS   = 77 * 256 * 768;
constexpr int VISION_ELEMS = 576 * 256 * 768;

// S / A scratch in gmem: [b][m=77][row container 576 words]
// before k2: fp32 logits; after k2: hi half2 pairs [0,288), lo pairs [288,576)
__device__ float g_S[256 * 77 * 576];

__device__ __forceinline__ float ex2f(float x) {
    float y; asm("ex2.approx.f32 %0, %1;" : "=f"(y) : "f"(x)); return y;
}

// split a float2 into hi (fp16x2) and lo (fp16x2 of residual), packed as u32
__device__ __forceinline__ void split2(float2 x, uint32_t& h, uint32_t& l) {
    __half hx = __float2half_rn(x.x), hy = __float2half_rn(x.y);
    __half lx = __float2half_rn(x.x - __half2float(hx));
    __half ly = __float2half_rn(x.y - __half2float(hy));
    h = (uint32_t)__half_as_ushort(hx) | ((uint32_t)__half_as_ushort(hy) << 16);
    l = (uint32_t)__half_as_ushort(lx) | ((uint32_t)__half_as_ushort(ly) << 16);
}

// fp16 m16n8k16, fp32 accumulate
__device__ __forceinline__ void mma16(float* c,
                                      uint32_t a0, uint32_t a1, uint32_t a2, uint32_t a3,
                                      uint32_t b0, uint32_t b1) {
    asm volatile(
        "mma.sync.aligned.m16n8k16.row.col.f32.f16.f16.f32 "
        "{%0,%1,%2,%3}, {%4,%5,%6,%7}, {%8,%9}, {%0,%1,%2,%3};\n"
        : "+f"(c[0]), "+f"(c[1]), "+f"(c[2]), "+f"(c[3])
        : "r"(a0), "r"(a1), "r"(a2), "r"(a3), "r"(b0), "r"(b1));
}

// ============== Kernel 1: S = T V^T (3xFP16), double-buffered ==============
// grid 768 = (b, nt). M=96(77 real) x N=192 per CTA. k-chunk = 32 floats (16 pairs).
// buffer layout (words): TH 0 (96x20) | TL 1920 | VH 3840 (192x20) | VL 7680
constexpr int K1_BUF   = 11520;            // words per buffer
constexpr int K1_BYTES = 2 * K1_BUF * 4;   // 92160 B

extern __shared__ float smdyn[];

__global__ __launch_bounds__(512, 1)
void k1_gemm1(const float* __restrict__ text, const float* __restrict__ vision) {
    uint32_t* smu = (uint32_t*)smdyn;
    const int b  = blockIdx.x / 3;
    const int nt = blockIdx.x % 3;
    const int nb = nt * 192;
    const float* tb = text + (size_t)b * Dd;
    const float* vb = vision + (size_t)b * Dd;

    const int tid  = threadIdx.x;
    const int w    = tid >> 5;    // 0..15
    const int lane = tid & 31;
    const int wm   = w >> 3;      // 0..1
    const int wn   = w & 7;       // 0..7
    const int g    = lane >> 2;
    const int c    = lane & 3;

    float acc[3][3][4];
    #pragma unroll
    for (int mt = 0; mt < 3; ++mt)
        #pragma unroll
        for (int nc = 0; nc < 3; ++nc)
            #pragma unroll
            for (int q = 0; q < 4; ++q) acc[mt][nc][q] = 0.f;

    float2 pT[3], pV[6];
    // prefetch chunk 0
    #pragma unroll
    for (int q = 0; q < 3; ++q) {
        int i = tid + 512 * q;            // T: 77 x 16 pairs = 1232
        if (i < 1232) {
            int m = i >> 4, j = i & 15;
            pT[q] = *(const float2*)(tb + (size_t)m * RS + 2 * j);
        }
    }
    #pragma unroll
    for (int q = 0; q < 6; ++q) {
        int i = tid + 512 * q;            // V: 192 x 16 = 3072
        int m = i >> 4, j = i & 15;
        pV[q] = *(const float2*)(vb + (size_t)(nb + m) * RS + 2 * j);
    }

    for (int dc = 0; dc < 24; ++dc) {
        const int bo = (dc & 1) * K1_BUF;

        // stage chunk dc into buf[dc&1]
        #pragma unroll
        for (int q = 0; q < 3; ++q) {
            int i = tid + 512 * q;
            if (i < 1232) {
                int m = i >> 4, j = i & 15;
                uint32_t h, l;
                split2(pT[q], h, l);
                smu[bo + m * 20 + j] = h;
                smu[bo + 1920 + m * 20 + j] = l;
            }
        }
        #pragma unroll
        for (int q = 0; q < 6; ++q) {
            int i = tid + 512 * q;
            int m = i >> 4, j = i & 15;
            uint32_t h, l;
            split2(pV[q], h, l);
            smu[bo + 3840 + m * 20 + j] = h;
            smu[bo + 7680 + m * 20 + j] = l;
        }

        // prefetch chunk dc+1 (consumed next iteration, full-interval shadow)
        if (dc < 23) {
            const int d0 = (dc + 1) * 32;
            #pragma unroll
            for (int q = 0; q < 3; ++q) {
                int i = tid + 512 * q;
                if (i < 1232) {
                    int m = i >> 4, j = i & 15;
                    pT[q] = *(const float2*)(tb + (size_t)m * RS + d0 + 2 * j);
                }
            }
            #pragma unroll
            for (int q = 0; q < 6; ++q) {
                int i = tid + 512 * q;
                int m = i >> 4, j = i & 15;
                pV[q] = *(const float2*)(vb + (size_t)(nb + m) * RS + d0 + 2 * j);
            }
        }

        __syncthreads();   // single barrier per interval

        // mma chunk dc from buf[dc&1]
        #pragma unroll
        for (int kk = 0; kk < 2; ++kk) {
            uint32_t bh0[3], bh1[3], bl0[3], bl1[3];
            #pragma unroll
            for (int nc = 0; nc < 3; ++nc) {
                int row = wn * 24 + nc * 8 + g;
                int ba  = bo + row * 20 + kk * 8 + c;
                bh0[nc] = smu[ba + 3840];     bh1[nc] = smu[ba + 3840 + 4];
                bl0[nc] = smu[ba + 7680];     bl1[nc] = smu[ba + 7680 + 4];
            }
            #pragma unroll
            for (int mt = 0; mt < 3; ++mt) {
                int r  = wm * 48 + mt * 16 + g;
                int aa = bo + r * 20 + kk * 8 + c;
                uint32_t ah0 = smu[aa];
                uint32_t ah1 = smu[aa + 8 * 20];
                uint32_t ah2 = smu[aa + 4];
                uint32_t ah3 = smu[aa + 8 * 20 + 4];
                uint32_t al0 = smu[aa + 1920];
                uint32_t al1 = smu[aa + 1920 + 8 * 20];
                uint32_t al2 = smu[aa + 1920 + 4];
                uint32_t al3 = smu[aa + 1920 + 8 * 20 + 4];
                #pragma unroll
                for (int nc = 0; nc < 3; ++nc) {
                    mma16(acc[mt][nc], ah0, ah1, ah2, ah3, bh0[nc], bh1[nc]);
                    mma16(acc[mt][nc], ah0, ah1, ah2, ah3, bl0[nc], bl1[nc]);
                    mma16(acc[mt][nc], al0, al1, al2, al3, bh0[nc], bh1[nc]);
                }
            }
        }
    }

    // epilogue: store S tile (fp32) to gmem scratch
    #pragma unroll
    for (int mt = 0; mt < 3; ++mt) {
        int r0 = wm * 48 + mt * 16 + g, r1 = r0 + 8;
        #pragma unroll
        for (int nc = 0; nc < 3; ++nc) {
            int col = nb + wn * 24 + nc * 8 + 2 * c;
            if (r0 < 77)
                *(float2*)&g_S[((size_t)b * 77 + r0) * 576 + col] =
                    make_float2(acc[mt][nc][0], acc[mt][nc][1]);
            if (r1 < 77)
                *(float2*)&g_S[((size_t)b * 77 + r1) * 576 + col] =
                    make_float2(acc[mt][nc][2], acc[mt][nc][3]);
        }
    }
}

// ===== Kernel 2: softmax (temp 0.07) over n=576, in place; writes pre-split A =====
__global__ __launch_bounds__(256, 8)
void k2_softmax() {
    const int w = threadIdx.x >> 5, lane = threadIdx.x & 31;
    const int row = blockIdx.x * 8 + w;       // 0..19711
    float* p = &g_S[(size_t)row * 576];
    uint32_t* pu = (uint32_t*)p;
    const float SCL = 20.60992915555662f;     // log2(e)/0.07

    float v[18];
    float mx = -1e30f;
    #pragma unroll
    for (int j = 0; j < 18; ++j) { v[j] = p[lane + 32 * j]; mx = fmaxf(mx, v[j]); }
    #pragma unroll
    for (int o = 16; o > 0; o >>= 1) mx = fmaxf(mx, __shfl_xor_sync(0xffffffffu, mx, o));
    float sum = 0.f;
    #pragma unroll
    for (int j = 0; j < 18; ++j) { v[j] = ex2f((v[j] - mx) * SCL); sum += v[j]; }
    #pragma unroll
    for (int o = 16; o > 0; o >>= 1) sum += __shfl_xor_sync(0xffffffffu, sum, o);
    const float rinv = 1.0f / sum;

    // lane <-> pair transpose via shfl with WARP-UNIFORM register indices.
    // Elements 64q..64q+63 live in v[2q] (idx lane+32*2q) and v[2q+1] (idx lane+32*(2q+1)).
    // Lane needs i0 = 2*lane + 64q and i1 = i0 + 1:
    //   i0 owner lane (2l)&31, register 2q if lane<16 else 2q+1
    //   i1 owner lane (2l+1)&31, register 2q if lane<16 else 2q+1
    #pragma unroll
    for (int q = 0; q < 9; ++q) {
        int s0 = (2 * lane) & 31;
        int s1 = (2 * lane + 1) & 31;
        float ea = __shfl_sync(0xffffffffu, v[2 * q],     s0);
        float eb = __shfl_sync(0xffffffffu, v[2 * q + 1], s0);
        float fa = __shfl_sync(0xffffffffu, v[2 * q],     s1);
        float fb = __shfl_sync(0xffffffffu, v[2 * q + 1], s1);
        float x = (lane < 16) ? ea : eb;
        float y = (lane < 16) ? fa : fb;
        uint32_t h, l;
        split2(make_float2(x * rinv, y * rinv), h, l);
        pu[lane + 32 * q] = h;                // hi plane [0,288)
        pu[288 + lane + 32 * q] = l;          // lo plane [288,576)
    }
}

// ============== Kernel 3: O = A V (3xFP16), A pre-split, V double-buffered ==============
// grid 256 (one CTA per batch), 512 thr. d-tile 128, n-chunk 32 (16 pairs).
// smem: A rows at r*580 (hi [0,288), lo [288,576)) = 44672 words;
// V buffers: [pair 16][d 128, stride 136], VH +0 (16x136=2176), VL +2176; buf = 4352 w.
constexpr int A_STR   = 580;
constexpr int K3_VB   = 77 * A_STR + 12;       // 44672 (V buffers start)
constexpr int K3_BUF  = 4352;
constexpr int K3_BYTES = (K3_VB + 2 * K3_BUF) * 4;   // 213504 B

__global__ __launch_bounds__(512, 1)
void k3_gemm2(const float* __restrict__ vision, float* __restrict__ out) {
    uint32_t* smu = (uint32_t*)smdyn;
    const int b = blockIdx.x;
    const float* vb = vision + (size_t)b * Dd;
    float* ob = out + (size_t)b * Dd;

    const int tid  = threadIdx.x;
    const int w    = tid >> 5;    // 0..15  (also: n-pair owner for staging)
    const int lane = tid & 31;
    const int wm   = w >> 3;
    const int wn   = w & 7;
    const int g    = lane >> 2;
    const int c    = lane & 3;

    // load pre-split A into smem (coalesced float4)
    {
        const float4* src = (const float4*)&g_S[(size_t)b * 77 * 576];
        #pragma unroll
        for (int q = 0; q < 22; ++q) {
            int i = tid + 512 * q;
            if (i < 11088) {                     // 77 * 144
                int m = i / 144, f = i % 144;
                *(float4*)&smdyn[m * A_STR + 4 * f] = src[(size_t)m * 144 + f];
            }
        }
    }

    int arow[3][2];
    #pragma unroll
    for (int mt = 0; mt < 3; ++mt) {
        int r0 = wm * 48 + mt * 16 + g;
        int r1 = r0 + 8;
        arow[mt][0] = (r0 > 76 ? 76 : r0) * A_STR;
        arow[mt][1] = (r1 > 76 ? 76 : r1) * A_STR;
    }

    float acc[3][2][4];
    #pragma unroll
    for (int mt = 0; mt < 3; ++mt)
        #pragma unroll
        for (int d8 = 0; d8 < 2; ++d8)
            #pragma unroll
            for (int q = 0; q < 4; ++q) acc[mt][d8][q] = 0.f;

    // prefetch step 0 (dt=0, ch=0): warp w = n-pair w, lanes sweep d (4x32)
    float pv0[4], pv1[4];
    {
        const float* r0p = vb + (size_t)(2 * w) * RS;
        const float* r1p = vb + (size_t)(2 * w + 1) * RS;
        #pragma unroll
        for (int it = 0; it < 4; ++it) {
            int d = lane + 32 * it;
            pv0[it] = r0p[d];
            pv1[it] = r1p[d];
        }
    }

    // 108 steps: s -> dt = s/18, ch = s%18
    int dt = 0, ch = 0;
    for (int s = 0; s < 108; ++s) {
        const int bo = K3_VB + (s & 1) * K3_BUF;

        // stage step s into buf[s&1]: [pair w][d] stride 136
        #pragma unroll
        for (int it = 0; it < 4; ++it) {
            int d = lane + 32 * it;
            uint32_t h, l;
            split2(make_float2(pv0[it], pv1[it]), h, l);
            smu[bo + w * 136 + d] = h;
            smu[bo + 2176 + w * 136 + d] = l;
        }

        // prefetch step s+1
        int ndt = dt, nch = ch + 1;
        if (nch == 18) { nch = 0; ndt = dt + 1; }
        if (s < 107) {
            const float* r0p = vb + (size_t)(nch * 32 + 2 * w) * RS + ndt * 128;
            const float* r1p = r0p + RS;
            #pragma unroll
            for (int it = 0; it < 4; ++it) {
                int d = lane + 32 * it;
                pv0[it] = r0p[d];
                pv1[it] = r1p[d];
            }
        }

        __syncthreads();   // single barrier per step

        // mma step s
        #pragma unroll
        for (int kk = 0; kk < 2; ++kk) {
            uint32_t bh0[2], bh1[2], bl0[2], bl1[2];
            #pragma unroll
            for (int d8 = 0; d8 < 2; ++d8) {
                int col = wn * 16 + d8 * 8 + g;
                int pa  = bo + (kk * 8 + c) * 136 + col;
                bh0[d8] = smu[pa];            bh1[d8] = smu[pa + 4 * 136];
                bl0[d8] = smu[pa + 2176];     bl1[d8] = smu[pa + 2176 + 4 * 136];
            }
            const int pb = ch * 16 + kk * 8 + c;
            #pragma unroll
            for (int mt = 0; mt < 3; ++mt) {
                uint32_t ah0 = smu[arow[mt][0] + pb];
                uint32_t ah1 = smu[arow[mt][1] + pb];
                uint32_t ah2 = smu[arow[mt][0] + pb + 4];
                uint32_t ah3 = smu[arow[mt][1] + pb + 4];
                uint32_t al0 = smu[arow[mt][0] + 288 + pb];
                uint32_t al1 = smu[arow[mt][1] + 288 + pb];
                uint32_t al2 = smu[arow[mt][0] + 288 + pb + 4];
                uint32_t al3 = smu[arow[mt][1] + 288 + pb + 4];
                #pragma unroll
                for (int d8 = 0; d8 < 2; ++d8) {
                    mma16(acc[mt][d8], ah0, ah1, ah2, ah3, bh0[d8], bh1[d8]);
                    mma16(acc[mt][d8], ah0, ah1, ah2, ah3, bl0[d8], bl1[d8]);
                    mma16(acc[mt][d8], al0, al1, al2, al3, bh0[d8], bh1[d8]);
                }
            }
        }

        // end of a d-tile: store output tile, reset acc
        if (ch == 17) {
            const int db = dt * 128;
            #pragma unroll
            for (int mt = 0; mt < 3; ++mt) {
                int r0 = wm * 48 + mt * 16 + g, r1 = r0 + 8;
                #pragma unroll
                for (int d8 = 0; d8 < 2; ++d8) {
                    int col = db + wn * 16 + d8 * 8 + 2 * c;
                    if (r0 < 77)
                        *(float2*)(ob + (size_t)r0 * RS + col) =
                            make_float2(acc[mt][d8][0], acc[mt][d8][1]);
                    if (r1 < 77)
                        *(float2*)(ob + (size_t)r1 * RS + col) =
                            make_float2(acc[mt][d8][2], acc[mt][d8][3]);
                    #pragma unroll
                    for (int q = 0; q < 4; ++q) acc[mt][d8][q] = 0.f;
                }
            }
        }
        dt = ndt; ch = nch;
    }
}

extern "C" void kernel_launch(void* const* d_in, const int* in_sizes, int n_in,
                              void* d_out, int out_size) {
    const float* text   = (const float*)d_in[0];
    const float* vision = (const float*)d_in[1];
    if (n_in >= 2 && in_sizes[0] == VISION_ELEMS && in_sizes[1] == TEXT_ELEMS) {
        const float* t = text; text = vision; vision = t;
    }
    cudaFuncSetAttribute(k1_gemm1, cudaFuncAttributeMaxDynamicSharedMemorySize, K1_BYTES);
    cudaFuncSetAttribute(k3_gemm2, cudaFuncAttributeMaxDynamicSharedMemorySize, K3_BYTES);

    k1_gemm1<<<768, 512, K1_BYTES>>>(text, vision);
    k2_softmax<<<2464, 256>>>();
    k3_gemm2<<<256, 512, K3_BYTES>>>(vision, (float*)d_out);
}

// round 11
// speedup vs baseline: 2.1852x; 1.1068x over previous
#include <cuda_runtime.h>
#include <cuda_fp16.h>
#include <cstdint>

// ---------------- problem constants ----------------
constexpr int Dd   = 768;
constexpr int RS   = 256 * 768;            // row stride in floats (B*D)
constexpr int TEXT_ELEMS   = 77 * 256 * 768;
constexpr int VISION_ELEMS = 576 * 256 * 768;

// S / A scratch in gmem: [b][m=77][row container 576 words]
// before k2: fp32 logits; after k2: fp16 half2 pairs in [0,288) of each row
__device__ float g_S[256 * 77 * 576];

__device__ __forceinline__ float ex2f(float x) {
    float y; asm("ex2.approx.f32 %0, %1;" : "=f"(y) : "f"(x)); return y;
}

// split a float2 into hi (fp16x2) and lo (fp16x2 of residual), packed as u32
__device__ __forceinline__ void split2(float2 x, uint32_t& h, uint32_t& l) {
    __half hx = __float2half_rn(x.x), hy = __float2half_rn(x.y);
    __half lx = __float2half_rn(x.x - __half2float(hx));
    __half ly = __float2half_rn(x.y - __half2float(hy));
    h = (uint32_t)__half_as_ushort(hx) | ((uint32_t)__half_as_ushort(hy) << 16);
    l = (uint32_t)__half_as_ushort(lx) | ((uint32_t)__half_as_ushort(ly) << 16);
}

__device__ __forceinline__ uint32_t pack2(float2 x) {
    __half hx = __float2half_rn(x.x), hy = __float2half_rn(x.y);
    return (uint32_t)__half_as_ushort(hx) | ((uint32_t)__half_as_ushort(hy) << 16);
}

// fp16 m16n8k16, fp32 accumulate
__device__ __forceinline__ void mma16(float* c,
                                      uint32_t a0, uint32_t a1, uint32_t a2, uint32_t a3,
                                      uint32_t b0, uint32_t b1) {
    asm volatile(
        "mma.sync.aligned.m16n8k16.row.col.f32.f16.f16.f32 "
        "{%0,%1,%2,%3}, {%4,%5,%6,%7}, {%8,%9}, {%0,%1,%2,%3};\n"
        : "+f"(c[0]), "+f"(c[1]), "+f"(c[2]), "+f"(c[3])
        : "r"(a0), "r"(a1), "r"(a2), "r"(a3), "r"(b0), "r"(b1));
}

// ============== Kernel 1: S = T V^T (3xFP16), double-buffered, 48x48 warp tile ==============
// grid 768 = (b, nt). M=96(77 real) x N=192 per CTA, 256 thr = 8 warps (2x4).
// k-chunk = 32 floats (16 pairs). buffer: TH 0 (96x20) | TL 1920 | VH 3840 (192x20) | VL 7680
constexpr int K1_BUF   = 11520;            // words per buffer
constexpr int K1_BYTES = 2 * K1_BUF * 4;   // 92160 B

extern __shared__ float smdyn[];

__global__ __launch_bounds__(256, 1)
void k1_gemm1(const float* __restrict__ text, const float* __restrict__ vision) {
    uint32_t* smu = (uint32_t*)smdyn;
    const int b  = blockIdx.x / 3;
    const int nt = blockIdx.x % 3;
    const int nb = nt * 192;
    const float* tb = text + (size_t)b * Dd;
    const float* vb = vision + (size_t)b * Dd;

    const int tid  = threadIdx.x;
    const int w    = tid >> 5;    // 0..7
    const int lane = tid & 31;
    const int wm   = w >> 2;      // 0..1
    const int wn   = w & 3;       // 0..3
    const int g    = lane >> 2;
    const int c    = lane & 3;

    float acc[3][6][4];
    #pragma unroll
    for (int mt = 0; mt < 3; ++mt)
        #pragma unroll
        for (int nc = 0; nc < 6; ++nc)
            #pragma unroll
            for (int q = 0; q < 4; ++q) acc[mt][nc][q] = 0.f;

    float2 pT[5], pV[12];
    // prefetch chunk 0 (chunk = 32 floats = 16 pairs)
    #pragma unroll
    for (int q = 0; q < 5; ++q) {
        int i = tid + 256 * q;            // T: 77 x 16 pairs = 1232
        if (i < 1232) {
            int m = i >> 4, j = i & 15;
            pT[q] = *(const float2*)(tb + (size_t)m * RS + 2 * j);
        }
    }
    #pragma unroll
    for (int q = 0; q < 12; ++q) {
        int i = tid + 256 * q;            // V: 192 x 16 = 3072
        int m = i >> 4, j = i & 15;
        pV[q] = *(const float2*)(vb + (size_t)(nb + m) * RS + 2 * j);
    }

    for (int dc = 0; dc < 24; ++dc) {
        const int bo = (dc & 1) * K1_BUF;

        // stage chunk dc into buf[dc&1]
        #pragma unroll
        for (int q = 0; q < 5; ++q) {
            int i = tid + 256 * q;
            if (i < 1232) {
                int m = i >> 4, j = i & 15;
                uint32_t h, l;
                split2(pT[q], h, l);
                smu[bo + m * 20 + j] = h;
                smu[bo + 1920 + m * 20 + j] = l;
            }
        }
        #pragma unroll
        for (int q = 0; q < 12; ++q) {
            int i = tid + 256 * q;
            int m = i >> 4, j = i & 15;
            uint32_t h, l;
            split2(pV[q], h, l);
            smu[bo + 3840 + m * 20 + j] = h;
            smu[bo + 7680 + m * 20 + j] = l;
        }

        // prefetch chunk dc+1
        if (dc < 23) {
            const int d0 = (dc + 1) * 32;
            #pragma unroll
            for (int q = 0; q < 5; ++q) {
                int i = tid + 256 * q;
                if (i < 1232) {
                    int m = i >> 4, j = i & 15;
                    pT[q] = *(const float2*)(tb + (size_t)m * RS + d0 + 2 * j);
                }
            }
            #pragma unroll
            for (int q = 0; q < 12; ++q) {
                int i = tid + 256 * q;
                int m = i >> 4, j = i & 15;
                pV[q] = *(const float2*)(vb + (size_t)(nb + m) * RS + d0 + 2 * j);
            }
        }

        __syncthreads();   // single barrier per interval

        // mma chunk dc from buf[dc&1]
        #pragma unroll
        for (int kk = 0; kk < 2; ++kk) {
            uint32_t bh0[6], bh1[6], bl0[6], bl1[6];
            #pragma unroll
            for (int nc = 0; nc < 6; ++nc) {
                int row = wn * 48 + nc * 8 + g;
                int ba  = bo + row * 20 + kk * 8 + c;
                bh0[nc] = smu[ba + 3840];     bh1[nc] = smu[ba + 3840 + 4];
                bl0[nc] = smu[ba + 7680];     bl1[nc] = smu[ba + 7680 + 4];
            }
            #pragma unroll
            for (int mt = 0; mt < 3; ++mt) {
                int r  = wm * 48 + mt * 16 + g;
                int aa = bo + r * 20 + kk * 8 + c;
                uint32_t ah0 = smu[aa];
                uint32_t ah1 = smu[aa + 8 * 20];
                uint32_t ah2 = smu[aa + 4];
                uint32_t ah3 = smu[aa + 8 * 20 + 4];
                uint32_t al0 = smu[aa + 1920];
                uint32_t al1 = smu[aa + 1920 + 8 * 20];
                uint32_t al2 = smu[aa + 1920 + 4];
                uint32_t al3 = smu[aa + 1920 + 8 * 20 + 4];
                #pragma unroll
                for (int nc = 0; nc < 6; ++nc) {
                    mma16(acc[mt][nc], ah0, ah1, ah2, ah3, bh0[nc], bh1[nc]);
                    mma16(acc[mt][nc], ah0, ah1, ah2, ah3, bl0[nc], bl1[nc]);
                    mma16(acc[mt][nc], al0, al1, al2, al3, bh0[nc], bh1[nc]);
                }
            }
        }
    }

    // epilogue: store S tile (fp32) to gmem scratch
    #pragma unroll
    for (int mt = 0; mt < 3; ++mt) {
        int r0 = wm * 48 + mt * 16 + g, r1 = r0 + 8;
        #pragma unroll
        for (int nc = 0; nc < 6; ++nc) {
            int col = nb + wn * 48 + nc * 8 + 2 * c;
            if (r0 < 77)
                *(float2*)&g_S[((size_t)b * 77 + r0) * 576 + col] =
                    make_float2(acc[mt][nc][0], acc[mt][nc][1]);
            if (r1 < 77)
                *(float2*)&g_S[((size_t)b * 77 + r1) * 576 + col] =
                    make_float2(acc[mt][nc][2], acc[mt][nc][3]);
        }
    }
}

// ===== Kernel 2: softmax (temp 0.07), in place; writes A as plain fp16 pairs =====
__global__ __launch_bounds__(256, 8)
void k2_softmax() {
    const int w = threadIdx.x >> 5, lane = threadIdx.x & 31;
    const int row = blockIdx.x * 8 + w;       // 0..19711
    float* p = &g_S[(size_t)row * 576];
    uint32_t* pu = (uint32_t*)p;
    const float SCL = 20.60992915555662f;     // log2(e)/0.07

    float v[18];
    float mx = -1e30f;
    #pragma unroll
    for (int j = 0; j < 18; ++j) { v[j] = p[lane + 32 * j]; mx = fmaxf(mx, v[j]); }
    #pragma unroll
    for (int o = 16; o > 0; o >>= 1) mx = fmaxf(mx, __shfl_xor_sync(0xffffffffu, mx, o));
    float sum = 0.f;
    #pragma unroll
    for (int j = 0; j < 18; ++j) { v[j] = ex2f((v[j] - mx) * SCL); sum += v[j]; }
    #pragma unroll
    for (int o = 16; o > 0; o >>= 1) sum += __shfl_xor_sync(0xffffffffu, sum, o);
    const float rinv = 1.0f / sum;

    // lane <-> pair transpose via shfl with warp-uniform register indices.
    // Elements 64q..64q+63 live in v[2q] / v[2q+1]. Lane needs i0=2*lane+64q, i1=i0+1.
    #pragma unroll
    for (int q = 0; q < 9; ++q) {
        int s0 = (2 * lane) & 31;
        int s1 = (2 * lane + 1) & 31;
        float ea = __shfl_sync(0xffffffffu, v[2 * q],     s0);
        float eb = __shfl_sync(0xffffffffu, v[2 * q + 1], s0);
        float fa = __shfl_sync(0xffffffffu, v[2 * q],     s1);
        float fb = __shfl_sync(0xffffffffu, v[2 * q + 1], s1);
        float x = (lane < 16) ? ea : eb;
        float y = (lane < 16) ? fa : fb;
        pu[lane + 32 * q] = pack2(make_float2(x * rinv, y * rinv));  // fp16 plane [0,288)
    }
}

// ====== Kernel 3: O = A V (2xFP16: ah*bh + ah*bl), A fp16, d-tile 192, double-buffered ======
// grid 256 (one CTA per batch), 512 thr. n-chunk 32 (16 pairs), 72 steps.
// smem: A rows at r*292 (fp16 pairs, 288 words + pad 4) = 22496 words (with pad12);
// V buffers: [pair 16][d 192, stride 200], VH +0 (3200), VL +3200; buf = 6400 w.
constexpr int A_STR   = 292;
constexpr int K3_VB   = 77 * A_STR + 12;       // 22496 (V buffers start)
constexpr int K3_BUF  = 6400;
constexpr int K3_BYTES = (K3_VB + 2 * K3_BUF) * 4;   // 141184 B

__global__ __launch_bounds__(512, 1)
void k3_gemm2(const float* __restrict__ vision, float* __restrict__ out) {
    uint32_t* smu = (uint32_t*)smdyn;
    const int b = blockIdx.x;
    const float* vb = vision + (size_t)b * Dd;
    float* ob = out + (size_t)b * Dd;

    const int tid  = threadIdx.x;
    const int w    = tid >> 5;    // 0..15  (n-pair owner for staging)
    const int lane = tid & 31;
    const int wm   = w >> 3;
    const int wn   = w & 7;
    const int g    = lane >> 2;
    const int c    = lane & 3;

    // load fp16 A into smem (coalesced float4): 77 rows x 72 float4
    {
        const float4* src = (const float4*)&g_S[(size_t)b * 77 * 576];
        #pragma unroll
        for (int q = 0; q < 11; ++q) {
            int i = tid + 512 * q;
            if (i < 5544) {                      // 77 * 72
                int m = i / 72, f = i % 72;
                *(float4*)&smdyn[m * A_STR + 4 * f] = src[(size_t)m * 144 + f];
            }
        }
    }

    int arow[3][2];
    #pragma unroll
    for (int mt = 0; mt < 3; ++mt) {
        int r0 = wm * 48 + mt * 16 + g;
        int r1 = r0 + 8;
        arow[mt][0] = (r0 > 76 ? 76 : r0) * A_STR;
        arow[mt][1] = (r1 > 76 ? 76 : r1) * A_STR;
    }

    float acc[3][3][4];
    #pragma unroll
    for (int mt = 0; mt < 3; ++mt)
        #pragma unroll
        for (int d8 = 0; d8 < 3; ++d8)
            #pragma unroll
            for (int q = 0; q < 4; ++q) acc[mt][d8][q] = 0.f;

    // prefetch step 0 (dt=0, ch=0): warp w = n-pair w, lanes sweep d (6x32)
    float pv0[6], pv1[6];
    {
        const float* r0p = vb + (size_t)(2 * w) * RS;
        const float* r1p = vb + (size_t)(2 * w + 1) * RS;
        #pragma unroll
        for (int it = 0; it < 6; ++it) {
            int d = lane + 32 * it;
            pv0[it] = r0p[d];
            pv1[it] = r1p[d];
        }
    }

    // 72 steps: s -> dt = s/18, ch = s%18
    int dt = 0, ch = 0;
    for (int s = 0; s < 72; ++s) {
        const int bo = K3_VB + (s & 1) * K3_BUF;

        // stage step s into buf[s&1]: [pair w][d] stride 200, hi/lo planes
        #pragma unroll
        for (int it = 0; it < 6; ++it) {
            int d = lane + 32 * it;
            uint32_t h, l;
            split2(make_float2(pv0[it], pv1[it]), h, l);
            smu[bo + w * 200 + d] = h;
            smu[bo + 3200 + w * 200 + d] = l;
        }

        // prefetch step s+1
        int ndt = dt, nch = ch + 1;
        if (nch == 18) { nch = 0; ndt = dt + 1; }
        if (s < 71) {
            const float* r0p = vb + (size_t)(nch * 32 + 2 * w) * RS + ndt * 192;
            const float* r1p = r0p + RS;
            #pragma unroll
            for (int it = 0; it < 6; ++it) {
                int d = lane + 32 * it;
                pv0[it] = r0p[d];
                pv1[it] = r1p[d];
            }
        }

        __syncthreads();   // single barrier per step

        // mma step s: 2 passes (ah*bh + ah*bl)
        #pragma unroll
        for (int kk = 0; kk < 2; ++kk) {
            uint32_t bh0[3], bh1[3], bl0[3], bl1[3];
            #pragma unroll
            for (int d8 = 0; d8 < 3; ++d8) {
                int col = wn * 24 + d8 * 8 + g;
                int pa  = bo + (kk * 8 + c) * 200 + col;
                bh0[d8] = smu[pa];            bh1[d8] = smu[pa + 4 * 200];
                bl0[d8] = smu[pa + 3200];     bl1[d8] = smu[pa + 3200 + 4 * 200];
            }
            const int pb = ch * 16 + kk * 8 + c;
            #pragma unroll
            for (int mt = 0; mt < 3; ++mt) {
                uint32_t ah0 = smu[arow[mt][0] + pb];
                uint32_t ah1 = smu[arow[mt][1] + pb];
                uint32_t ah2 = smu[arow[mt][0] + pb + 4];
                uint32_t ah3 = smu[arow[mt][1] + pb + 4];
                #pragma unroll
                for (int d8 = 0; d8 < 3; ++d8) {
                    mma16(acc[mt][d8], ah0, ah1, ah2, ah3, bh0[d8], bh1[d8]);
                    mma16(acc[mt][d8], ah0, ah1, ah2, ah3, bl0[d8], bl1[d8]);
                }
            }
        }

        // end of a d-tile: store output tile, reset acc
        if (ch == 17) {
            const int db = dt * 192;
            #pragma unroll
            for (int mt = 0; mt < 3; ++mt) {
                int r0 = wm * 48 + mt * 16 + g, r1 = r0 + 8;
                #pragma unroll
                for (int d8 = 0; d8 < 3; ++d8) {
                    int col = db + wn * 24 + d8 * 8 + 2 * c;
                    if (r0 < 77)
                        *(float2*)(ob + (size_t)r0 * RS + col) =
                            make_float2(acc[mt][d8][0], acc[mt][d8][1]);
                    if (r1 < 77)
                        *(float2*)(ob + (size_t)r1 * RS + col) =
                            make_float2(acc[mt][d8][2], acc[mt][d8][3]);
                    #pragma unroll
                    for (int q = 0; q < 4; ++q) acc[mt][d8][q] = 0.f;
                }
            }
        }
        dt = ndt; ch = nch;
    }
}

extern "C" void kernel_launch(void* const* d_in, const int* in_sizes, int n_in,
                              void* d_out, int out_size) {
    const float* text   = (const float*)d_in[0];
    const float* vision = (const float*)d_in[1];
    if (n_in >= 2 && in_sizes[0] == VISION_ELEMS && in_sizes[1] == TEXT_ELEMS) {
        const float* t = text; text = vision; vision = t;
    }
    cudaFuncSetAttribute(k1_gemm1, cudaFuncAttributeMaxDynamicSharedMemorySize, K1_BYTES);
    cudaFuncSetAttribute(k3_gemm2, cudaFuncAttributeMaxDynamicSharedMemorySize, K3_BYTES);

    k1_gemm1<<<768, 256, K1_BYTES>>>(text, vision);
    k2_softmax<<<2464, 256>>>();
    k3_gemm2<<<256, 512, K3_BYTES>>>(vision, (float*)d_out);
}